// round 6
// baseline (speedup 1.0000x reference)
#include <cuda_runtime.h>
#include <cstdint>
#include <cstddef>

#define N_TOK 16384
#define HID   768
#define INTER 3072
#define NHEAD 12
#define DH    64
#define WWIN  256
#define MIDW  (3*HID + INTER)   // 5376 (GEMM1 output width)
#define QKVW  (3*HID)           // 2304 (stored q|k|v width)
#define COMBW (HID + INTER)     // 3840

typedef unsigned long long u64;

// ---------------- scratch (static device globals; no allocation) ----------------
__device__ float g_xn [(size_t)N_TOK * HID];          // fp32 LN output (residual)
__device__ float g_xnt[(size_t)N_TOK * HID];          // tf32-rounded LN output (GEMM1 A)
__device__ float g_mid[(size_t)N_TOK * QKVW];         // q|k|v (roped, q pre-scaled)
__device__ float g_comb[(size_t)N_TOK * COMBW];       // attn|gelu(ff), tf32-rounded (GEMM2 A)
__device__ float g_wi[(size_t)HID * MIDW];            // tf32-rounded w_in
__device__ float g_wo[(size_t)COMBW * HID];           // tf32-rounded w_out

// ---------------- helpers ----------------
__device__ __forceinline__ float tf32r(float x) {
    uint32_t u;
    asm volatile("cvt.rna.tf32.f32 %0, %1;\n" : "=r"(u) : "f"(x));
    return __uint_as_float(u);
}
__device__ __forceinline__ void cp_async16(void* smem, const void* gmem) {
    unsigned s = (unsigned)__cvta_generic_to_shared(smem);
    asm volatile("cp.async.cg.shared.global [%0], [%1], 16;\n" :: "r"(s), "l"(gmem) : "memory");
}
__device__ __forceinline__ u64 pk2(float a, float b) {
    u64 r; asm("mov.b64 %0, {%1, %2};" : "=l"(r) : "f"(a), "f"(b)); return r;
}
__device__ __forceinline__ void unpk2(u64 v, float& a, float& b) {
    asm("mov.b64 {%0, %1}, %2;" : "=f"(a), "=f"(b) : "l"(v));
}
__device__ __forceinline__ u64 fma2_(u64 a, u64 b, u64 c) {
    u64 d; asm("fma.rn.f32x2 %0, %1, %2, %3;" : "=l"(d) : "l"(a), "l"(b), "l"(c)); return d;
}
__device__ __forceinline__ u64 mul2_(u64 a, u64 b) {
    u64 d; asm("mul.rn.f32x2 %0, %1, %2;" : "=l"(d) : "l"(a), "l"(b)); return d;
}
__device__ __forceinline__ float gelu_f(float x) {
    return 0.5f * x * (1.0f + tanhf(0.7978845608028654f * (x + 0.044715f * x * x * x)));
}

// ---------------- tf32 rounding of weights ----------------
__global__ void round_tf32_kernel(const float* __restrict__ src, float* __restrict__ dst, int count) {
    int i = blockIdx.x * blockDim.x + threadIdx.x;
    if (i < count) dst[i] = tf32r(src[i]);
}

// ---------------- LayerNorm ----------------
__global__ __launch_bounds__(256) void ln_kernel(
    const float* __restrict__ x, const float* __restrict__ sc, const float* __restrict__ of,
    float* __restrict__ xn, float* __restrict__ xnt)
{
    int row = blockIdx.x, tid = threadIdx.x;
    const float* xr = x + (size_t)row * HID;
    float v0 = xr[tid], v1 = xr[tid + 256], v2 = xr[tid + 512];
    float s = v0 + v1 + v2;
    float ss = v0*v0 + v1*v1 + v2*v2;
    __shared__ float rs[8], rss[8];
    #pragma unroll
    for (int o = 16; o; o >>= 1) {
        s  += __shfl_xor_sync(0xffffffffu, s,  o);
        ss += __shfl_xor_sync(0xffffffffu, ss, o);
    }
    if ((tid & 31) == 0) { rs[tid >> 5] = s; rss[tid >> 5] = ss; }
    __syncthreads();
    s = 0.f; ss = 0.f;
    #pragma unroll
    for (int i = 0; i < 8; i++) { s += rs[i]; ss += rss[i]; }
    float mu  = s * (1.0f / HID);
    float var = ss * (1.0f / HID) - mu * mu;
    float inv = rsqrtf(var + 1e-5f);
    float* xo = xn  + (size_t)row * HID;
    float* xt = xnt + (size_t)row * HID;
    float y0 = (v0 - mu) * inv * sc[tid]       + of[tid];
    float y1 = (v1 - mu) * inv * sc[tid + 256] + of[tid + 256];
    float y2 = (v2 - mu) * inv * sc[tid + 512] + of[tid + 512];
    xo[tid] = y0;       xt[tid] = tf32r(y0);
    xo[tid + 256] = y1; xt[tid + 256] = tf32r(y1);
    xo[tid + 512] = y2; xt[tid + 512] = tf32r(y2);
}

// ---------------- TF32 GEMM, 128x128x16 tile, double-buffered cp.async ----------------
// MODE 0: GEMM1. C = A@B + bias, epilogue: cols<1536 -> RoPE -> mid (q scaled 0.125);
//         1536..2303 -> mid; >=2304 -> gelu -> tf32r -> comb[:, HID + (col-2304)]
// MODE 1: GEMM2. C = A@B + bias + resid -> out
__device__ __forceinline__ void gemm_load_stage(
    const float* __restrict__ A, const float* __restrict__ B,
    int N, int K, int bm, int bn, int k0, int tid,
    float (*As)[20], float (*Bs)[136])
{
    #pragma unroll
    for (int i = 0; i < 2; i++) {              // A: 128x16 = 512 float4
        int f = tid + i * 256;
        int r = f >> 2, c4 = f & 3;
        cp_async16(&As[r][c4 * 4], &A[(size_t)(bm + r) * K + k0 + c4 * 4]);
    }
    #pragma unroll
    for (int i = 0; i < 2; i++) {              // B: 16x128 = 512 float4
        int f = tid + i * 256;
        int r = f >> 5, c4 = f & 31;
        cp_async16(&Bs[r][c4 * 4], &B[(size_t)(k0 + r) * N + bn + c4 * 4]);
    }
}

template <int MODE>
__global__ __launch_bounds__(256) void gemm_tf32_kernel(
    const float* __restrict__ A, const float* __restrict__ B,
    const float* __restrict__ bias, const float* __restrict__ resid,
    const float* __restrict__ psin, const float* __restrict__ pcos,
    float* __restrict__ C, float* __restrict__ C2, int M, int N, int K)
{
    __shared__ float As[2][128][20];
    __shared__ float Bs[2][16][136];

    int tid = threadIdx.x;
    int bm = blockIdx.y * 128, bn = blockIdx.x * 128;
    int warp = tid >> 5, lane = tid & 31;
    int wm = (warp >> 2) * 64;
    int wn = (warp & 3) * 32;
    int g = lane >> 2, tg = lane & 3;

    float acc[4][4][4];
    #pragma unroll
    for (int a = 0; a < 4; a++)
        #pragma unroll
        for (int b = 0; b < 4; b++)
            #pragma unroll
            for (int c = 0; c < 4; c++) acc[a][b][c] = 0.f;

    gemm_load_stage(A, B, N, K, bm, bn, 0, tid, As[0], Bs[0]);
    asm volatile("cp.async.commit_group;\n" ::: "memory");

    int KT = K >> 4;
    for (int kt = 0; kt < KT; kt++) {
        int cur = kt & 1;
        if (kt + 1 < KT) {
            gemm_load_stage(A, B, N, K, bm, bn, (kt + 1) << 4, tid, As[cur ^ 1], Bs[cur ^ 1]);
            asm volatile("cp.async.commit_group;\n" ::: "memory");
            asm volatile("cp.async.wait_group 1;\n" ::: "memory");
        } else {
            asm volatile("cp.async.wait_group 0;\n" ::: "memory");
        }
        __syncthreads();

        #pragma unroll
        for (int ks = 0; ks < 2; ks++) {
            uint32_t af[4][4], bf[4][2];
            #pragma unroll
            for (int mt = 0; mt < 4; mt++) {
                int r = wm + mt * 16 + g;
                int cc = ks * 8 + tg;
                af[mt][0] = __float_as_uint(As[cur][r][cc]);
                af[mt][1] = __float_as_uint(As[cur][r + 8][cc]);
                af[mt][2] = __float_as_uint(As[cur][r][cc + 4]);
                af[mt][3] = __float_as_uint(As[cur][r + 8][cc + 4]);
            }
            #pragma unroll
            for (int nt = 0; nt < 4; nt++) {
                int cc = wn + nt * 8 + g;
                bf[nt][0] = __float_as_uint(Bs[cur][ks * 8 + tg][cc]);
                bf[nt][1] = __float_as_uint(Bs[cur][ks * 8 + tg + 4][cc]);
            }
            #pragma unroll
            for (int mt = 0; mt < 4; mt++)
                #pragma unroll
                for (int nt = 0; nt < 4; nt++)
                    asm volatile(
                        "mma.sync.aligned.m16n8k8.row.col.f32.tf32.tf32.f32 "
                        "{%0,%1,%2,%3}, {%4,%5,%6,%7}, {%8,%9}, {%0,%1,%2,%3};\n"
                        : "+f"(acc[mt][nt][0]), "+f"(acc[mt][nt][1]),
                          "+f"(acc[mt][nt][2]), "+f"(acc[mt][nt][3])
                        : "r"(af[mt][0]), "r"(af[mt][1]), "r"(af[mt][2]), "r"(af[mt][3]),
                          "r"(bf[nt][0]), "r"(bf[nt][1]));
        }
        __syncthreads();
    }

    #pragma unroll
    for (int mt = 0; mt < 4; mt++) {
        #pragma unroll
        for (int nt = 0; nt < 4; nt++) {
            int row = bm + wm + mt * 16 + g;
            int col = bn + wn + nt * 8 + tg * 2;
            float2 bv = *(const float2*)&bias[col];
            float o0 = acc[mt][nt][0] + bv.x;
            float o1 = acc[mt][nt][1] + bv.y;
            float o2 = acc[mt][nt][2] + bv.x;
            float o3 = acc[mt][nt][3] + bv.y;
            if constexpr (MODE == 1) {
                float2 r0 = *(const float2*)&resid[(size_t)row * N + col];
                float2 r1 = *(const float2*)&resid[(size_t)(row + 8) * N + col];
                o0 += r0.x; o1 += r0.y; o2 += r1.x; o3 += r1.y;
                *(float2*)&C[(size_t)row * N + col]       = make_float2(o0, o1);
                *(float2*)&C[(size_t)(row + 8) * N + col] = make_float2(o2, o3);
            } else {
                if (col < 2 * HID) {
                    // RoPE: pair (col even, col+1). d within head.
                    int d = col & (DH - 1);
                    float sa0 = psin[row * DH + d],       sa1 = psin[row * DH + d + 1];
                    float ca0 = pcos[row * DH + d],       ca1 = pcos[row * DH + d + 1];
                    float sb0 = psin[(row + 8) * DH + d], sb1 = psin[(row + 8) * DH + d + 1];
                    float cb0 = pcos[(row + 8) * DH + d], cb1 = pcos[(row + 8) * DH + d + 1];
                    float sc = (col < HID) ? 0.125f : 1.0f;   // q pre-scaled by 1/sqrt(DH)
                    float r00 = (o0 * ca0 - o1 * sa0) * sc;
                    float r01 = (o1 * ca1 + o0 * sa1) * sc;
                    float r10 = (o2 * cb0 - o3 * sb0) * sc;
                    float r11 = (o3 * cb1 + o2 * sb1) * sc;
                    *(float2*)&C[(size_t)row * QKVW + col]       = make_float2(r00, r01);
                    *(float2*)&C[(size_t)(row + 8) * QKVW + col] = make_float2(r10, r11);
                } else if (col < 3 * HID) {
                    *(float2*)&C[(size_t)row * QKVW + col]       = make_float2(o0, o1);
                    *(float2*)&C[(size_t)(row + 8) * QKVW + col] = make_float2(o2, o3);
                } else {
                    int cc = HID + (col - 3 * HID);
                    *(float2*)&C2[(size_t)row * COMBW + cc] =
                        make_float2(tf32r(gelu_f(o0)), tf32r(gelu_f(o1)));
                    *(float2*)&C2[(size_t)(row + 8) * COMBW + cc] =
                        make_float2(tf32r(gelu_f(o2)), tf32r(gelu_f(o3)));
                }
            }
        }
    }
}

// ---------------- chunked local attention, f32x2-packed, thread per query ----------------
__global__ __launch_bounds__(128, 3) void attn_kernel(
    const float* __restrict__ mid, const int* __restrict__ lenp, float* __restrict__ comb)
{
    __shared__ float4 Ks[64][16];
    __shared__ float4 Vs[64][16];
    int tid = threadIdx.x;
    int h = blockIdx.y;
    int cblk = blockIdx.x;
    int n = cblk * 128 + tid;
    unsigned lm = ~((unsigned)(*lenp) - 1u);
    unsigned nseq = (unsigned)n & lm;

    u64 q2[32];
    {
        const float4* qp = (const float4*)&mid[(size_t)n * QKVW + h * DH];
        #pragma unroll
        for (int i = 0; i < 16; i++) {
            float4 v = qp[i];
            q2[2*i]   = pk2(v.x, v.y);
            q2[2*i+1] = pk2(v.z, v.w);
        }
    }
    u64 O2[32];
    #pragma unroll
    for (int i = 0; i < 32; i++) O2[i] = 0ull;
    float m = -1e30f, l = 0.f;

    for (int t = 0; t < 6; t++) {
        int j0 = cblk * 128 - 256 + t * 64;
        #pragma unroll
        for (int i = 0; i < 8; i++) {
            int f = tid + i * 128;            // 0..1023
            int r = f >> 4, c4 = f & 15;
            int jg = j0 + r;
            float4 kv = make_float4(0.f,0.f,0.f,0.f), vv = kv;
            if (jg >= 0) {
                kv = *(const float4*)&mid[(size_t)jg * QKVW +   HID + h * DH + c4 * 4];
                vv = *(const float4*)&mid[(size_t)jg * QKVW + 2*HID + h * DH + c4 * 4];
            }
            Ks[r][c4] = kv;
            Vs[r][c4] = vv;
        }
        __syncthreads();

        if (j0 <= n && j0 + 63 >= n - (WWIN - 1)) {
            #pragma unroll 1
            for (int j = 0; j < 64; j++) {
                int jg = j0 + j;
                int dd = n - jg;
                bool ok = (jg >= 0) && (dd >= 0) && (dd < WWIN) &&
                          (((unsigned)jg & lm) == nseq);
                if (!ok) continue;
                u64 a0 = 0ull, a1 = 0ull, a2 = 0ull, a3 = 0ull;
                const float4* kp = Ks[j];
                #pragma unroll
                for (int i = 0; i < 16; i += 2) {
                    float4 k0 = kp[i], k1 = kp[i + 1];
                    a0 = fma2_(q2[2*i],   pk2(k0.x, k0.y), a0);
                    a1 = fma2_(q2[2*i+1], pk2(k0.z, k0.w), a1);
                    a2 = fma2_(q2[2*i+2], pk2(k1.x, k1.y), a2);
                    a3 = fma2_(q2[2*i+3], pk2(k1.z, k1.w), a3);
                }
                float x0,x1,y0,y1,z0,z1,w0,w1;
                unpk2(a0,x0,x1); unpk2(a1,y0,y1); unpk2(a2,z0,z1); unpk2(a3,w0,w1);
                float s = ((x0+x1)+(y0+y1)) + ((z0+z1)+(w0+w1));
                float mn = fmaxf(m, s);
                if (mn != m) {
                    float sc = __expf(m - mn);
                    u64 sc2 = pk2(sc, sc);
                    l *= sc;
                    #pragma unroll
                    for (int i = 0; i < 32; i++) O2[i] = mul2_(O2[i], sc2);
                    m = mn;
                }
                float p = __expf(s - m);
                l += p;
                u64 pp = pk2(p, p);
                const float4* vp = Vs[j];
                #pragma unroll
                for (int i = 0; i < 16; i++) {
                    float4 v = vp[i];
                    O2[2*i]   = fma2_(pp, pk2(v.x, v.y), O2[2*i]);
                    O2[2*i+1] = fma2_(pp, pk2(v.z, v.w), O2[2*i+1]);
                }
            }
        }
        __syncthreads();
    }

    float inv = 1.0f / l;
    float* op = &comb[(size_t)n * COMBW + h * DH];
    #pragma unroll
    for (int i = 0; i < 32; i++) {
        float a, b; unpk2(O2[i], a, b);
        op[2*i]   = tf32r(a * inv);
        op[2*i+1] = tf32r(b * inv);
    }
}

// ---------------- launch ----------------
extern "C" void kernel_launch(void* const* d_in, const int* in_sizes, int n_in,
                              void* d_out, int out_size)
{
    const float* x     = (const float*)d_in[0];
    // d_in[1] normed_ages: unused by reference
    const float* psin  = (const float*)d_in[2];
    const float* pcos  = (const float*)d_in[3];
    const float* lns   = (const float*)d_in[4];
    const float* lno   = (const float*)d_in[5];
    const float* w_in  = (const float*)d_in[6];
    const float* b_in  = (const float*)d_in[7];
    const float* w_out = (const float*)d_in[8];
    const float* b_out = (const float*)d_in[9];
    const int*   lenp  = (const int*)d_in[10];
    float* out = (float*)d_out;

    float *xn, *xnt, *mid, *comb, *wi, *wo;
    cudaGetSymbolAddress((void**)&xn,   g_xn);
    cudaGetSymbolAddress((void**)&xnt,  g_xnt);
    cudaGetSymbolAddress((void**)&mid,  g_mid);
    cudaGetSymbolAddress((void**)&comb, g_comb);
    cudaGetSymbolAddress((void**)&wi,   g_wi);
    cudaGetSymbolAddress((void**)&wo,   g_wo);

    round_tf32_kernel<<<(HID * MIDW + 255) / 256, 256>>>(w_in, wi, HID * MIDW);
    round_tf32_kernel<<<(COMBW * HID + 255) / 256, 256>>>(w_out, wo, COMBW * HID);

    ln_kernel<<<N_TOK, 256>>>(x, lns, lno, xn, xnt);

    // GEMM1: fused bias + RoPE (q,k) + gelu(ff)->comb
    gemm_tf32_kernel<0><<<dim3(MIDW / 128, N_TOK / 128), 256>>>(
        xnt, wi, b_in, nullptr, psin, pcos, mid, comb, N_TOK, MIDW, HID);

    attn_kernel<<<dim3(N_TOK / 128, NHEAD), 128>>>(mid, lenp, comb);

    // GEMM2: fused bias + residual
    gemm_tf32_kernel<1><<<dim3(HID / 128, N_TOK / 128), 256>>>(
        comb, wo, b_out, xn, nullptr, nullptr, out, nullptr, N_TOK, HID, COMBW);
}

// round 7
// speedup vs baseline: 1.3809x; 1.3809x over previous
#include <cuda_runtime.h>
#include <cstdint>
#include <cstddef>

#define N_TOK 16384
#define HID   768
#define INTER 3072
#define NHEAD 12
#define DH    64
#define WWIN  256
#define MIDW  (3*HID + INTER)   // 5376 (GEMM1 output width)
#define QKVW  (3*HID)           // 2304 (stored q|k|v width)
#define COMBW (HID + INTER)     // 3840

// ---------------- scratch (static device globals; no allocation) ----------------
__device__ float g_xn [(size_t)N_TOK * HID];          // fp32 LN output (residual)
__device__ float g_xnt[(size_t)N_TOK * HID];          // tf32-rounded LN output (GEMM1 A)
__device__ float g_mid[(size_t)N_TOK * QKVW];         // q|k|v (roped, q pre-scaled)
__device__ float g_comb[(size_t)N_TOK * COMBW];       // attn|gelu(ff), tf32-rounded (GEMM2 A)
__device__ float g_wi[(size_t)HID * MIDW];            // tf32-rounded w_in
__device__ float g_wo[(size_t)COMBW * HID];           // tf32-rounded w_out

// ---------------- helpers ----------------
__device__ __forceinline__ float tf32r(float x) {
    uint32_t u;
    asm volatile("cvt.rna.tf32.f32 %0, %1;\n" : "=r"(u) : "f"(x));
    return __uint_as_float(u);
}
__device__ __forceinline__ void cp_async16(void* smem, const void* gmem) {
    unsigned s = (unsigned)__cvta_generic_to_shared(smem);
    asm volatile("cp.async.cg.shared.global [%0], [%1], 16;\n" :: "r"(s), "l"(gmem) : "memory");
}
__device__ __forceinline__ float gelu_f(float x) {
    return 0.5f * x * (1.0f + tanhf(0.7978845608028654f * (x + 0.044715f * x * x * x)));
}

// ---------------- tf32 rounding of weights ----------------
__global__ void round_tf32_kernel(const float* __restrict__ src, float* __restrict__ dst, int count) {
    int i = blockIdx.x * blockDim.x + threadIdx.x;
    if (i < count) dst[i] = tf32r(src[i]);
}

// ---------------- LayerNorm ----------------
__global__ __launch_bounds__(256) void ln_kernel(
    const float* __restrict__ x, const float* __restrict__ sc, const float* __restrict__ of,
    float* __restrict__ xn, float* __restrict__ xnt)
{
    int row = blockIdx.x, tid = threadIdx.x;
    const float* xr = x + (size_t)row * HID;
    float v0 = xr[tid], v1 = xr[tid + 256], v2 = xr[tid + 512];
    float s = v0 + v1 + v2;
    float ss = v0*v0 + v1*v1 + v2*v2;
    __shared__ float rs[8], rss[8];
    #pragma unroll
    for (int o = 16; o; o >>= 1) {
        s  += __shfl_xor_sync(0xffffffffu, s,  o);
        ss += __shfl_xor_sync(0xffffffffu, ss, o);
    }
    if ((tid & 31) == 0) { rs[tid >> 5] = s; rss[tid >> 5] = ss; }
    __syncthreads();
    s = 0.f; ss = 0.f;
    #pragma unroll
    for (int i = 0; i < 8; i++) { s += rs[i]; ss += rss[i]; }
    float mu  = s * (1.0f / HID);
    float var = ss * (1.0f / HID) - mu * mu;
    float inv = rsqrtf(var + 1e-5f);
    float* xo = xn  + (size_t)row * HID;
    float* xt = xnt + (size_t)row * HID;
    float y0 = (v0 - mu) * inv * sc[tid]       + of[tid];
    float y1 = (v1 - mu) * inv * sc[tid + 256] + of[tid + 256];
    float y2 = (v2 - mu) * inv * sc[tid + 512] + of[tid + 512];
    xo[tid] = y0;       xt[tid] = tf32r(y0);
    xo[tid + 256] = y1; xt[tid + 256] = tf32r(y1);
    xo[tid + 512] = y2; xt[tid + 512] = tf32r(y2);
}

// ---------------- TF32 GEMM, 128x128x16 tile, double-buffered cp.async ----------------
// MODE 0: GEMM1. C = A@B + bias; epilogue: cols<1536 -> RoPE -> mid (q scaled 0.125);
//         1536..2303 -> mid; >=2304 -> gelu -> tf32r -> comb[:, HID + (col-2304)]
// MODE 1: GEMM2. C = A@B + bias + resid -> out
__device__ __forceinline__ void gemm_load_stage(
    const float* __restrict__ A, const float* __restrict__ B,
    int N, int K, int bm, int bn, int k0, int tid,
    float (*As)[20], float (*Bs)[136])
{
    #pragma unroll
    for (int i = 0; i < 2; i++) {              // A: 128x16 = 512 float4
        int f = tid + i * 256;
        int r = f >> 2, c4 = f & 3;
        cp_async16(&As[r][c4 * 4], &A[(size_t)(bm + r) * K + k0 + c4 * 4]);
    }
    #pragma unroll
    for (int i = 0; i < 2; i++) {              // B: 16x128 = 512 float4
        int f = tid + i * 256;
        int r = f >> 5, c4 = f & 31;
        cp_async16(&Bs[r][c4 * 4], &B[(size_t)(k0 + r) * N + bn + c4 * 4]);
    }
}

template <int MODE>
__global__ __launch_bounds__(256) void gemm_tf32_kernel(
    const float* __restrict__ A, const float* __restrict__ B,
    const float* __restrict__ bias, const float* __restrict__ resid,
    const float* __restrict__ psin, const float* __restrict__ pcos,
    float* __restrict__ C, float* __restrict__ C2, int M, int N, int K)
{
    __shared__ float As[2][128][20];
    __shared__ float Bs[2][16][136];

    int tid = threadIdx.x;
    int bm = blockIdx.y * 128, bn = blockIdx.x * 128;
    int warp = tid >> 5, lane = tid & 31;
    int wm = (warp >> 2) * 64;
    int wn = (warp & 3) * 32;
    int g = lane >> 2, tg = lane & 3;

    float acc[4][4][4];
    #pragma unroll
    for (int a = 0; a < 4; a++)
        #pragma unroll
        for (int b = 0; b < 4; b++)
            #pragma unroll
            for (int c = 0; c < 4; c++) acc[a][b][c] = 0.f;

    gemm_load_stage(A, B, N, K, bm, bn, 0, tid, As[0], Bs[0]);
    asm volatile("cp.async.commit_group;\n" ::: "memory");

    int KT = K >> 4;
    for (int kt = 0; kt < KT; kt++) {
        int cur = kt & 1;
        if (kt + 1 < KT) {
            gemm_load_stage(A, B, N, K, bm, bn, (kt + 1) << 4, tid, As[cur ^ 1], Bs[cur ^ 1]);
            asm volatile("cp.async.commit_group;\n" ::: "memory");
            asm volatile("cp.async.wait_group 1;\n" ::: "memory");
        } else {
            asm volatile("cp.async.wait_group 0;\n" ::: "memory");
        }
        __syncthreads();

        #pragma unroll
        for (int ks = 0; ks < 2; ks++) {
            uint32_t af[4][4], bf[4][2];
            #pragma unroll
            for (int mt = 0; mt < 4; mt++) {
                int r = wm + mt * 16 + g;
                int cc = ks * 8 + tg;
                af[mt][0] = __float_as_uint(As[cur][r][cc]);
                af[mt][1] = __float_as_uint(As[cur][r + 8][cc]);
                af[mt][2] = __float_as_uint(As[cur][r][cc + 4]);
                af[mt][3] = __float_as_uint(As[cur][r + 8][cc + 4]);
            }
            #pragma unroll
            for (int nt = 0; nt < 4; nt++) {
                int cc = wn + nt * 8 + g;
                bf[nt][0] = __float_as_uint(Bs[cur][ks * 8 + tg][cc]);
                bf[nt][1] = __float_as_uint(Bs[cur][ks * 8 + tg + 4][cc]);
            }
            #pragma unroll
            for (int mt = 0; mt < 4; mt++)
                #pragma unroll
                for (int nt = 0; nt < 4; nt++)
                    asm volatile(
                        "mma.sync.aligned.m16n8k8.row.col.f32.tf32.tf32.f32 "
                        "{%0,%1,%2,%3}, {%4,%5,%6,%7}, {%8,%9}, {%0,%1,%2,%3};\n"
                        : "+f"(acc[mt][nt][0]), "+f"(acc[mt][nt][1]),
                          "+f"(acc[mt][nt][2]), "+f"(acc[mt][nt][3])
                        : "r"(af[mt][0]), "r"(af[mt][1]), "r"(af[mt][2]), "r"(af[mt][3]),
                          "r"(bf[nt][0]), "r"(bf[nt][1]));
        }
        __syncthreads();
    }

    #pragma unroll
    for (int mt = 0; mt < 4; mt++) {
        #pragma unroll
        for (int nt = 0; nt < 4; nt++) {
            int row = bm + wm + mt * 16 + g;
            int col = bn + wn + nt * 8 + tg * 2;
            float2 bv = *(const float2*)&bias[col];
            float o0 = acc[mt][nt][0] + bv.x;
            float o1 = acc[mt][nt][1] + bv.y;
            float o2 = acc[mt][nt][2] + bv.x;
            float o3 = acc[mt][nt][3] + bv.y;
            if constexpr (MODE == 1) {
                float2 r0 = *(const float2*)&resid[(size_t)row * N + col];
                float2 r1 = *(const float2*)&resid[(size_t)(row + 8) * N + col];
                o0 += r0.x; o1 += r0.y; o2 += r1.x; o3 += r1.y;
                *(float2*)&C[(size_t)row * N + col]       = make_float2(o0, o1);
                *(float2*)&C[(size_t)(row + 8) * N + col] = make_float2(o2, o3);
            } else {
                if (col < 2 * HID) {
                    // RoPE: pair (col even, col+1). d within head.
                    int d = col & (DH - 1);
                    float sa0 = psin[row * DH + d],       sa1 = psin[row * DH + d + 1];
                    float ca0 = pcos[row * DH + d],       ca1 = pcos[row * DH + d + 1];
                    float sb0 = psin[(row + 8) * DH + d], sb1 = psin[(row + 8) * DH + d + 1];
                    float cb0 = pcos[(row + 8) * DH + d], cb1 = pcos[(row + 8) * DH + d + 1];
                    float sc = (col < HID) ? 0.125f : 1.0f;   // q pre-scaled by 1/sqrt(DH)
                    float r00 = (o0 * ca0 - o1 * sa0) * sc;
                    float r01 = (o1 * ca1 + o0 * sa1) * sc;
                    float r10 = (o2 * cb0 - o3 * sb0) * sc;
                    float r11 = (o3 * cb1 + o2 * sb1) * sc;
                    *(float2*)&C[(size_t)row * QKVW + col]       = make_float2(r00, r01);
                    *(float2*)&C[(size_t)(row + 8) * QKVW + col] = make_float2(r10, r11);
                } else if (col < 3 * HID) {
                    *(float2*)&C[(size_t)row * QKVW + col]       = make_float2(o0, o1);
                    *(float2*)&C[(size_t)(row + 8) * QKVW + col] = make_float2(o2, o3);
                } else {
                    int cc = HID + (col - 3 * HID);
                    *(float2*)&C2[(size_t)row * COMBW + cc] =
                        make_float2(tf32r(gelu_f(o0)), tf32r(gelu_f(o1)));
                    *(float2*)&C2[(size_t)(row + 8) * COMBW + cc] =
                        make_float2(tf32r(gelu_f(o2)), tf32r(gelu_f(o3)));
                }
            }
        }
    }
}

// ---------------- chunked local attention: CTA per (chunk, head), thread per query ----------------
// Round-5 design (measured-good), adapted to QKVW stride.
__global__ __launch_bounds__(256) void attn_kernel(
    const float* __restrict__ mid, const int* __restrict__ lenp, float* __restrict__ comb)
{
    __shared__ float Ks[64][64];
    __shared__ float Vs[64][64];
    int tid = threadIdx.x;
    int h = blockIdx.y;
    int cblk = blockIdx.x;
    int n = cblk * 256 + tid;
    unsigned lm = ~((unsigned)(*lenp) - 1u);
    unsigned nseq = (unsigned)n & lm;

    float q[64];
    {
        const float4* qp = (const float4*)&mid[(size_t)n * QKVW + h * DH];
        #pragma unroll
        for (int i = 0; i < 16; i++) {
            float4 v = qp[i];
            q[4*i] = v.x; q[4*i+1] = v.y; q[4*i+2] = v.z; q[4*i+3] = v.w;
        }
    }
    float O[64];
    #pragma unroll
    for (int d = 0; d < 64; d++) O[d] = 0.f;
    float m = -1e30f, l = 0.f;

    for (int t = 0; t < 8; t++) {
        int j0 = cblk * 256 - 256 + t * 64;
        // cooperative K/V tile load (zeros for j<0; masked anyway)
        #pragma unroll
        for (int i = 0; i < 4; i++) {
            int f = tid + i * 256;           // 0..1023 float4s
            int r = f >> 4, c4 = f & 15;
            int jg = j0 + r;
            float4 kv = make_float4(0.f,0.f,0.f,0.f), vv = kv;
            if (jg >= 0) {
                kv = *(const float4*)&mid[(size_t)jg * QKVW +   HID + h * DH + c4 * 4];
                vv = *(const float4*)&mid[(size_t)jg * QKVW + 2*HID + h * DH + c4 * 4];
            }
            *(float4*)&Ks[r][c4 * 4] = kv;
            *(float4*)&Vs[r][c4 * 4] = vv;
        }
        __syncthreads();

        if (j0 <= n && j0 + 63 >= n - (WWIN - 1)) {
            #pragma unroll 1
            for (int j = 0; j < 64; j++) {
                int jg = j0 + j;
                int dd = n - jg;
                bool ok = (jg >= 0) && (dd >= 0) && (dd < WWIN) &&
                          (((unsigned)jg & lm) == nseq);
                if (!ok) continue;
                float s0 = 0.f, s1 = 0.f, s2 = 0.f, s3 = 0.f;
                const float4* kp = (const float4*)Ks[j];
                #pragma unroll
                for (int i = 0; i < 16; i++) {
                    float4 kv = kp[i];
                    s0 = fmaf(q[4*i],   kv.x, s0);
                    s1 = fmaf(q[4*i+1], kv.y, s1);
                    s2 = fmaf(q[4*i+2], kv.z, s2);
                    s3 = fmaf(q[4*i+3], kv.w, s3);
                }
                float s = (s0 + s1) + (s2 + s3);
                float mn = fmaxf(m, s);
                float p  = __expf(s - mn);
                float sc = __expf(m - mn);
                if (sc != 1.0f) {
                    l *= sc;
                    #pragma unroll
                    for (int d = 0; d < 64; d++) O[d] *= sc;
                }
                m = mn;
                l += p;
                const float4* vp = (const float4*)Vs[j];
                #pragma unroll
                for (int i = 0; i < 16; i++) {
                    float4 vv = vp[i];
                    O[4*i]   = fmaf(p, vv.x, O[4*i]);
                    O[4*i+1] = fmaf(p, vv.y, O[4*i+1]);
                    O[4*i+2] = fmaf(p, vv.z, O[4*i+2]);
                    O[4*i+3] = fmaf(p, vv.w, O[4*i+3]);
                }
            }
        }
        __syncthreads();
    }

    float inv = 1.0f / l;
    float* op = &comb[(size_t)n * COMBW + h * DH];
    #pragma unroll
    for (int d = 0; d < 64; d++) op[d] = tf32r(O[d] * inv);
}

// ---------------- launch ----------------
extern "C" void kernel_launch(void* const* d_in, const int* in_sizes, int n_in,
                              void* d_out, int out_size)
{
    const float* x     = (const float*)d_in[0];
    // d_in[1] normed_ages: unused by reference
    const float* psin  = (const float*)d_in[2];
    const float* pcos  = (const float*)d_in[3];
    const float* lns   = (const float*)d_in[4];
    const float* lno   = (const float*)d_in[5];
    const float* w_in  = (const float*)d_in[6];
    const float* b_in  = (const float*)d_in[7];
    const float* w_out = (const float*)d_in[8];
    const float* b_out = (const float*)d_in[9];
    const int*   lenp  = (const int*)d_in[10];
    float* out = (float*)d_out;

    float *xn, *xnt, *mid, *comb, *wi, *wo;
    cudaGetSymbolAddress((void**)&xn,   g_xn);
    cudaGetSymbolAddress((void**)&xnt,  g_xnt);
    cudaGetSymbolAddress((void**)&mid,  g_mid);
    cudaGetSymbolAddress((void**)&comb, g_comb);
    cudaGetSymbolAddress((void**)&wi,   g_wi);
    cudaGetSymbolAddress((void**)&wo,   g_wo);

    round_tf32_kernel<<<(HID * MIDW + 255) / 256, 256>>>(w_in, wi, HID * MIDW);
    round_tf32_kernel<<<(COMBW * HID + 255) / 256, 256>>>(w_out, wo, COMBW * HID);

    ln_kernel<<<N_TOK, 256>>>(x, lns, lno, xn, xnt);

    // GEMM1: fused bias + RoPE (q,k) + gelu(ff)->comb
    gemm_tf32_kernel<0><<<dim3(MIDW / 128, N_TOK / 128), 256>>>(
        xnt, wi, b_in, nullptr, psin, pcos, mid, comb, N_TOK, MIDW, HID);

    attn_kernel<<<dim3(N_TOK / 256, NHEAD), 256>>>(mid, lenp, comb);

    // GEMM2: fused bias + residual
    gemm_tf32_kernel<1><<<dim3(HID / 128, N_TOK / 128), 256>>>(
        comb, wo, b_out, xn, nullptr, nullptr, out, nullptr, N_TOK, HID, COMBW);
}